// round 6
// baseline (speedup 1.0000x reference)
#include <cuda_runtime.h>
#include <math.h>

#define DD    1024
#define KK    32      // elements per thread
#define PAD   33      // padded shared stride (conflict-free transpose)
#define WARPS 8
#define STACK 4

// In-register FWHT over the 5 bits of the register index k.
// lane-minor layout (v[k] = elem k*32+lane): covers strides 32..512.
// contiguous layout (v[k] = elem lane*32+k): covers strides 1..16.
__device__ __forceinline__ void fwht_reg(float v[KK]) {
#pragma unroll
    for (int b = 1; b < KK; b <<= 1) {
#pragma unroll
        for (int k = 0; k < KK; k++) {
            if ((k & b) == 0) {
                float a0 = v[k], a1 = v[k | b];
                v[k]     = a0 + a1;
                v[k | b] = a0 - a1;
            }
        }
    }
}

// minBlocksPerMultiprocessor = 1: let ptxas use enough registers to keep
// v[32] resident. R3's default cap (64 regs) spilled v[] to local memory,
// inflating L1tex traffic ~5x (L1=90.3% busy, issue=20.7%).
__global__ __launch_bounds__(WARPS * 32, 1)
void FastFoodLayerDense_kernel(const float* __restrict__ x,
                               const float* __restrict__ Bm,
                               const float* __restrict__ G,
                               const float* __restrict__ S,
                               const float* __restrict__ bias,
                               const int*   __restrict__ P,
                               float*       __restrict__ out,
                               int nrows)
{
    __shared__ float sh[WARPS][KK * PAD];   // 33.8 KB static

    const int warp = threadIdx.x >> 5;
    const int lane = threadIdx.x & 31;
    const int unit = blockIdx.x * WARPS + warp;   // (row, stack) pair
    const int row  = unit >> 2;
    const int s    = unit & 3;
    if (row >= nrows) return;                     // warp-uniform

    float* shw = sh[warp];
    const float* xr = x  + (size_t)row * DD;
    const float* Bs = Bm + s * DD;

    float v[KK];

    // ---- load x * B, lane-minor layout: v[k] = element (k*32 + lane) ----
#pragma unroll
    for (int k = 0; k < KK; k++) {
        int e = k * 32 + lane;
        v[k] = xr[e] * Bs[e];
    }

    // ---- WHT #1: high strides (32..512) in registers ----
    fwht_reg(v);

    // ---- transpose lane-minor -> contiguous via padded shared ----
    __syncwarp();
#pragma unroll
    for (int k = 0; k < KK; k++) shw[k * PAD + lane] = v[k];   // elem k*32+lane
    __syncwarp();
#pragma unroll
    for (int k = 0; k < KK; k++) v[k] = shw[lane * PAD + k];   // elem lane*32+k

    // ---- WHT #1: low strides (1..16) in registers ----
    fwht_reg(v);

    // ---- stage WHT1 result to shared (padded by element index), gather * G ----
    __syncwarp();
#pragma unroll
    for (int k = 0; k < KK; k++) shw[lane * PAD + k] = v[k];   // elem lane*32+k at e+(e>>5)
    __syncwarp();

    const int*   Ps = P + s * DD;
    const float* Gs = G + s * DD;
#pragma unroll
    for (int k = 0; k < KK; k++) {
        int e = lane * 32 + k;
        int p = Ps[e] - s * DD;            // P segment s maps within stack s
        v[k] = shw[p + (p >> 5)] * Gs[e];  // sh[(p>>5)*33 + (p&31)]
    }

    // ---- WHT #2: low strides (contiguous layout) ----
    fwht_reg(v);

    // ---- transpose contiguous -> lane-minor ----
    __syncwarp();
#pragma unroll
    for (int k = 0; k < KK; k++) shw[lane * PAD + k] = v[k];   // elem lane*32+k
    __syncwarp();
#pragma unroll
    for (int k = 0; k < KK; k++) v[k] = shw[k * PAD + lane];   // elem k*32+lane

    // ---- WHT #2: high strides ----
    fwht_reg(v);

    // ---- scale, cos/sin (fast intrinsic), coalesced stores ----
    const float* Ss  = S + s * DD;
    float* orow      = out + (size_t)row * (2 * STACK * DD);
    const float scale = 0.03125f;   // 1/(sigma*sqrt(D)) = 1/32
    const float amp   = 0.03125f;   // sqrt(1/D) = 1/32
#pragma unroll
    for (int k = 0; k < KK; k++) {
        int e = k * 32 + lane;
        float h = v[k] * (scale * Ss[e]);
        float sn, cs;
        __sincosf(h, &sn, &cs);
        int oc = s * DD + e;
        orow[oc]              = fmaf(amp, cs, bias[oc]);
        orow[STACK * DD + oc] = fmaf(amp, sn, bias[STACK * DD + oc]);
    }
}

extern "C" void kernel_launch(void* const* d_in, const int* in_sizes, int n_in,
                              void* d_out, int out_size)
{
    // metadata order: x, B, G, S, bias, H (unused), P
    const float* x    = (const float*)d_in[0];
    const float* Bm   = (const float*)d_in[1];
    const float* G    = (const float*)d_in[2];
    const float* S    = (const float*)d_in[3];
    const float* bias = (const float*)d_in[4];
    const int*   P    = (const int*)  d_in[6];

    int nrows  = in_sizes[0] / DD;          // 8192
    int units  = nrows * STACK;             // 32768 warps
    int blocks = (units + WARPS - 1) / WARPS;

    FastFoodLayerDense_kernel<<<blocks, WARPS * 32>>>(
        x, Bm, G, S, bias, P, (float*)d_out, nrows);
}

// round 7
// speedup vs baseline: 1.9460x; 1.9460x over previous
#include <cuda_runtime.h>
#include <math.h>

#define DD      1024
#define KK      16      // elements per thread
#define UNIT_T  64      // threads per (row,stack) unit (2 warps)
#define UNITS   4       // units per block
#define THREADS 256
#define STACK   4
#define SHPAD   (DD + DD / 32)   // 1056: every 32 floats padded by 1

// In-register FWHT over the 4 bits of k.
// B layout (v[k] = elem t*16+k): strides 1,2,4,8.
// A layout (v[k] = elem k*64+t): strides 64,128,256,512.
__device__ __forceinline__ void fwht_reg16(float v[KK]) {
#pragma unroll
    for (int b = 1; b < KK; b <<= 1) {
#pragma unroll
        for (int k = 0; k < KK; k++) {
            if ((k & b) == 0) {
                float a0 = v[k], a1 = v[k | b];
                v[k]     = a0 + a1;
                v[k | b] = a0 - a1;
            }
        }
    }
}

// Cross-lane butterfly for element strides 16*m (m = 1 or 2) in B layout:
// elem = t*16+k, so elem bit (4+log2 m) == lane bit log2 m.
__device__ __forceinline__ void fwht_shfl(float v[KK], int lane, int m) {
#pragma unroll
    for (int k = 0; k < KK; k++) {
        float w = __shfl_xor_sync(0xffffffffu, v[k], m);
        v[k] = (lane & m) ? (w - v[k]) : (v[k] + w);
    }
}

__global__ __launch_bounds__(THREADS, 3)   // <=85 regs, 24 warps/SM
void FastFoodLayerDense_kernel(const float* __restrict__ x,
                               const float* __restrict__ Bm,
                               const float* __restrict__ G,
                               const float* __restrict__ S,
                               const float* __restrict__ bias,
                               const int*   __restrict__ P,
                               float*       __restrict__ out,
                               int nrows)
{
    __shared__ float sh[UNITS][SHPAD];   // 16.9 KB

    const int tid  = threadIdx.x;
    const int u    = tid >> 6;           // unit within block
    const int t    = tid & 63;           // thread within unit
    const int lane = tid & 31;
    const int unit = blockIdx.x * UNITS + u;   // (row, stack)
    const int row  = unit >> 2;
    const int s    = unit & 3;

    float* shu = sh[u];

    // Padded address helpers (addr = e + e/32):
    //  B layout e = t*16+k  -> 16*t + (t>>1) + k   (conflict-free, proven)
    //  A layout e = k*64+t  -> 66*k + t + (t>>5)   (lane-consecutive)
    const int bBase = 16 * t + (t >> 1);
    const int aOff  = t + (t >> 5);

    float v[KK];

    // ---- load x*B, B layout, fully vectorized ----
    const float4* x4 = (const float4*)(x + (size_t)row * DD);
    const float4* B4 = (const float4*)(Bm + s * DD);
#pragma unroll
    for (int j = 0; j < 4; j++) {
        float4 xv = x4[t * 4 + j];
        float4 bv = B4[t * 4 + j];
        v[4 * j + 0] = xv.x * bv.x;
        v[4 * j + 1] = xv.y * bv.y;
        v[4 * j + 2] = xv.z * bv.z;
        v[4 * j + 3] = xv.w * bv.w;
    }

    // ---- WHT #1 low: strides 1..8 (reg) + 16,32 (shfl) ----
    fwht_reg16(v);
    fwht_shfl(v, lane, 1);
    fwht_shfl(v, lane, 2);

    // ---- transpose B -> A ----
#pragma unroll
    for (int k = 0; k < KK; k++) shu[bBase + k] = v[k];
    __syncthreads();
#pragma unroll
    for (int k = 0; k < KK; k++) v[k] = shu[66 * k + aOff];

    // ---- WHT #1 high: strides 64..512 ----
    fwht_reg16(v);

    // ---- stage WHT1 result element-ordered for the gather ----
    __syncthreads();                               // WAR on shu
#pragma unroll
    for (int k = 0; k < KK; k++) shu[66 * k + aOff] = v[k];
    __syncthreads();

    // ---- permute-gather * G, A layout (P,G reads coalesced) ----
    const int*   Ps = P + s * DD;
    const float* Gs = G + s * DD;
#pragma unroll
    for (int k = 0; k < KK; k++) {
        int e = k * 64 + t;
        int p = Ps[e] - s * DD;            // segment s maps within stack s
        v[k] = shu[p + (p >> 5)] * Gs[e];
    }

    // ---- WHT #2 high: strides 64..512 (A layout) ----
    fwht_reg16(v);

    // ---- transpose A -> B ----
    __syncthreads();                               // WAR on shu
#pragma unroll
    for (int k = 0; k < KK; k++) shu[66 * k + aOff] = v[k];
    __syncthreads();
#pragma unroll
    for (int k = 0; k < KK; k++) v[k] = shu[bBase + k];

    // ---- WHT #2 low: strides 1..8 (reg) + 16,32 (shfl) ----
    fwht_reg16(v);
    fwht_shfl(v, lane, 1);
    fwht_shfl(v, lane, 2);

    // ---- scale, cos/sin, vectorized stores (B layout: per-thread contiguous) ----
    const float4* S4  = (const float4*)(S + s * DD);
    const float4* bc4 = (const float4*)(bias + s * DD);
    const float4* bs4 = (const float4*)(bias + STACK * DD + s * DD);
    float*  orow = out + (size_t)row * (2 * STACK * DD);
    float4* oc4  = (float4*)(orow + s * DD);
    float4* os4  = (float4*)(orow + STACK * DD + s * DD);
    const float scale = 0.03125f;   // 1/(sigma*sqrt(D))
    const float amp   = 0.03125f;   // sqrt(1/D)
#pragma unroll
    for (int j = 0; j < 4; j++) {
        float4 sv = S4[t * 4 + j];
        float4 bc = bc4[t * 4 + j];
        float4 bs = bs4[t * 4 + j];
        float4 co, si;
        float sn, cs;
        __sincosf(v[4 * j + 0] * (scale * sv.x), &sn, &cs);
        co.x = fmaf(amp, cs, bc.x);  si.x = fmaf(amp, sn, bs.x);
        __sincosf(v[4 * j + 1] * (scale * sv.y), &sn, &cs);
        co.y = fmaf(amp, cs, bc.y);  si.y = fmaf(amp, sn, bs.y);
        __sincosf(v[4 * j + 2] * (scale * sv.z), &sn, &cs);
        co.z = fmaf(amp, cs, bc.z);  si.z = fmaf(amp, sn, bs.z);
        __sincosf(v[4 * j + 3] * (scale * sv.w), &sn, &cs);
        co.w = fmaf(amp, cs, bc.w);  si.w = fmaf(amp, sn, bs.w);
        oc4[t * 4 + j] = co;
        os4[t * 4 + j] = si;
    }
}

extern "C" void kernel_launch(void* const* d_in, const int* in_sizes, int n_in,
                              void* d_out, int out_size)
{
    // metadata order: x, B, G, S, bias, H (unused), P
    const float* x    = (const float*)d_in[0];
    const float* Bm   = (const float*)d_in[1];
    const float* G    = (const float*)d_in[2];
    const float* S    = (const float*)d_in[3];
    const float* bias = (const float*)d_in[4];
    const int*   P    = (const int*)  d_in[6];

    int nrows  = in_sizes[0] / DD;          // 8192
    int blocks = nrows;                     // 4 units/block, 4 stacks/row

    FastFoodLayerDense_kernel<<<blocks, THREADS>>>(
        x, Bm, G, S, bias, P, (float*)d_out, nrows);
}

// round 9
// speedup vs baseline: 2.2828x; 1.1731x over previous
#include <cuda_runtime.h>
#include <math.h>

#define DD      1024
#define KK      16      // elements per thread per row
#define UNITS   4       // units per block (one per stack)
#define THREADS 256
#define STACK   4
#define PAD     33      // R6-proven padded stride unit: addr(e) = e + (e>>5)
#define SHSZ    (KK * 2 * PAD)   // 1056 floats per buffer

// In-register FWHT over the 4 bits of k.
// B layout (v[k] = elem t*16+k): element bits 0-3 (strides 1,2,4,8).
// A layout (v[k] = elem k*64+t): element bits 6-9 (strides 64..512).
__device__ __forceinline__ void fwht_reg16(float v[KK]) {
#pragma unroll
    for (int b = 1; b < KK; b <<= 1) {
#pragma unroll
        for (int k = 0; k < KK; k++) {
            if ((k & b) == 0) {
                float a0 = v[k], a1 = v[k | b];
                v[k]     = a0 + a1;
                v[k | b] = a0 - a1;
            }
        }
    }
}

// Cross-lane butterfly for element bits 4,5 (= lane bits 0,1) in B layout.
__device__ __forceinline__ void fwht_shfl(float v[KK], int lane, int m) {
#pragma unroll
    for (int k = 0; k < KK; k++) {
        float w = __shfl_xor_sync(0xffffffffu, v[k], m);
        v[k] = (lane & m) ? (w - v[k]) : (v[k] + w);
    }
}

__global__ __launch_bounds__(THREADS, 2)   // <=128 regs; v0+v1 resident
void FastFoodLayerDense_kernel(const float* __restrict__ x,
                               const float* __restrict__ Bm,
                               const float* __restrict__ G,
                               const float* __restrict__ S,
                               const float* __restrict__ bias,
                               const int*   __restrict__ P,
                               float*       __restrict__ out,
                               int nrows)
{
    // two buffers per unit (row0 / row1), R6 addressing
    __shared__ float sh[UNITS][2][SHSZ];   // 33.8 KB

    const int tid  = threadIdx.x;
    const int u    = tid >> 6;                 // unit within block
    const int t    = tid & 63;                 // thread within unit
    const int lane = tid & 31;
    const int s    = u;                        // stack = unit index
    const int r0   = blockIdx.x * 2;
    const int r1   = r0 + 1;
    const bool has1 = (r1 < nrows);

    float* sh0 = sh[u][0];
    float* sh1 = sh[u][1];

    // addr(e) = e + (e>>5)  (R6-proven):
    //  B layout e = t*16+k -> 16t + (t>>1) + k     (e>>5 == t>>1, const over k)
    //  A layout e = k*64+t -> 66k + t + (t>>5)     (lane-consecutive)
    const int bBase = 16 * t + (t >> 1);
    const int aOff  = t + (t >> 5);

    float v0[KK], v1[KK];

    // ===== load x*B (B layout, vectorized global; B loaded once per pair) =====
    const float4* x0v = (const float4*)(x + (size_t)r0 * DD);
    const float4* x1v = (const float4*)(x + (size_t)r1 * DD);
    const float4* Bv  = (const float4*)(Bm + s * DD);
#pragma unroll
    for (int j = 0; j < 4; j++) {
        float4 bv = Bv[t * 4 + j];
        float4 a  = x0v[t * 4 + j];
        v0[4*j+0] = a.x * bv.x;  v0[4*j+1] = a.y * bv.y;
        v0[4*j+2] = a.z * bv.z;  v0[4*j+3] = a.w * bv.w;
        float4 b  = has1 ? x1v[t * 4 + j] : make_float4(0.f, 0.f, 0.f, 0.f);
        v1[4*j+0] = b.x * bv.x;  v1[4*j+1] = b.y * bv.y;
        v1[4*j+2] = b.z * bv.z;  v1[4*j+3] = b.w * bv.w;
    }

    // ===== WHT #1 low: bits 0-3 (reg) + 4,5 (shfl) =====
    fwht_reg16(v0);  fwht_reg16(v1);
    fwht_shfl(v0, lane, 1);  fwht_shfl(v1, lane, 1);
    fwht_shfl(v0, lane, 2);  fwht_shfl(v1, lane, 2);

    // ===== RT1: B -> A (scalar shared ops, R6 scheme) =====
#pragma unroll
    for (int k = 0; k < KK; k++) {
        sh0[bBase + k] = v0[k];
        sh1[bBase + k] = v1[k];
    }
    __syncthreads();
#pragma unroll
    for (int k = 0; k < KK; k++) {
        v0[k] = sh0[66 * k + aOff];
        v1[k] = sh1[66 * k + aOff];
    }

    // ===== WHT #1 high: bits 6-9 =====
    fwht_reg16(v0);  fwht_reg16(v1);

    // ===== RT2: stage element-ordered, then permute-gather * G =====
    __syncthreads();                       // WAR on buffers
#pragma unroll
    for (int k = 0; k < KK; k++) {
        sh0[66 * k + aOff] = v0[k];
        sh1[66 * k + aOff] = v1[k];
    }
    __syncthreads();

    const int*   Ps = P + s * DD;
    const float* Gs = G + s * DD;
#pragma unroll
    for (int k = 0; k < KK; k++) {
        int e = k * 64 + t;
        int p = Ps[e] - s * DD;            // segment s maps within stack s
        int pp = p + (p >> 5);
        float g = Gs[e];                   // P,G loaded once, used for both rows
        v0[k] = sh0[pp] * g;
        v1[k] = sh1[pp] * g;
    }

    // ===== WHT #2 high: bits 6-9 (A layout) =====
    fwht_reg16(v0);  fwht_reg16(v1);

    // ===== RT3: A -> B =====
    __syncthreads();                       // WAR on buffers
#pragma unroll
    for (int k = 0; k < KK; k++) {
        sh0[66 * k + aOff] = v0[k];
        sh1[66 * k + aOff] = v1[k];
    }
    __syncthreads();
#pragma unroll
    for (int k = 0; k < KK; k++) {
        v0[k] = sh0[bBase + k];
        v1[k] = sh1[bBase + k];
    }

    // ===== WHT #2 low: bits 0-3 (reg) + 4,5 (shfl) =====
    fwht_reg16(v0);  fwht_reg16(v1);
    fwht_shfl(v0, lane, 1);  fwht_shfl(v1, lane, 1);
    fwht_shfl(v0, lane, 2);  fwht_shfl(v1, lane, 2);

    // ===== scale, cos/sin, vectorized stores (S/bias loaded once per pair) =====
    const float4* S4  = (const float4*)(S + s * DD);
    const float4* bc4 = (const float4*)(bias + s * DD);
    const float4* bs4 = (const float4*)(bias + STACK * DD + s * DD);
    float*  o0   = out + (size_t)r0 * (2 * STACK * DD);
    float*  o1   = out + (size_t)r1 * (2 * STACK * DD);
    float4* oc0  = (float4*)(o0 + s * DD);
    float4* os0  = (float4*)(o0 + STACK * DD + s * DD);
    float4* oc1  = (float4*)(o1 + s * DD);
    float4* os1  = (float4*)(o1 + STACK * DD + s * DD);
    const float scale = 0.03125f;   // 1/(sigma*sqrt(D))
    const float amp   = 0.03125f;   // sqrt(1/D)
#pragma unroll
    for (int j = 0; j < 4; j++) {
        float4 sv = S4[t * 4 + j];
        float4 bc = bc4[t * 4 + j];
        float4 bs = bs4[t * 4 + j];
        float sn, cs;
        float4 co, si;
        // row 0
        __sincosf(v0[4*j+0] * (scale * sv.x), &sn, &cs);
        co.x = fmaf(amp, cs, bc.x);  si.x = fmaf(amp, sn, bs.x);
        __sincosf(v0[4*j+1] * (scale * sv.y), &sn, &cs);
        co.y = fmaf(amp, cs, bc.y);  si.y = fmaf(amp, sn, bs.y);
        __sincosf(v0[4*j+2] * (scale * sv.z), &sn, &cs);
        co.z = fmaf(amp, cs, bc.z);  si.z = fmaf(amp, sn, bs.z);
        __sincosf(v0[4*j+3] * (scale * sv.w), &sn, &cs);
        co.w = fmaf(amp, cs, bc.w);  si.w = fmaf(amp, sn, bs.w);
        oc0[t * 4 + j] = co;
        os0[t * 4 + j] = si;
        // row 1
        if (has1) {
            __sincosf(v1[4*j+0] * (scale * sv.x), &sn, &cs);
            co.x = fmaf(amp, cs, bc.x);  si.x = fmaf(amp, sn, bs.x);
            __sincosf(v1[4*j+1] * (scale * sv.y), &sn, &cs);
            co.y = fmaf(amp, cs, bc.y);  si.y = fmaf(amp, sn, bs.y);
            __sincosf(v1[4*j+2] * (scale * sv.z), &sn, &cs);
            co.z = fmaf(amp, cs, bc.z);  si.z = fmaf(amp, sn, bs.z);
            __sincosf(v1[4*j+3] * (scale * sv.w), &sn, &cs);
            co.w = fmaf(amp, cs, bc.w);  si.w = fmaf(amp, sn, bs.w);
            oc1[t * 4 + j] = co;
            os1[t * 4 + j] = si;
        }
    }
}

extern "C" void kernel_launch(void* const* d_in, const int* in_sizes, int n_in,
                              void* d_out, int out_size)
{
    // metadata order: x, B, G, S, bias, H (unused), P
    const float* x    = (const float*)d_in[0];
    const float* Bm   = (const float*)d_in[1];
    const float* G    = (const float*)d_in[2];
    const float* S    = (const float*)d_in[3];
    const float* bias = (const float*)d_in[4];
    const int*   P    = (const int*)  d_in[6];

    int nrows    = in_sizes[0] / DD;          // 8192
    int blocks   = (nrows + 1) / 2;           // one row-pair per block

    FastFoodLayerDense_kernel<<<blocks, THREADS>>>(
        x, Bm, G, S, bias, P, (float*)d_out, nrows);
}

// round 11
// speedup vs baseline: 2.7181x; 1.1907x over previous
#include <cuda_runtime.h>
#include <math.h>

#define DD      1024
#define KK      16      // elements per thread per row
#define RR      4       // rows per unit (quad batching)
#define UNITS   2       // stack-units per block
#define THREADS 128
#define STACK   4
#define SHSZ    (KK * 2 * 33)   // 1056 floats per row-buffer (PAD-33 scheme)

// In-register FWHT over the 4 bits of k.
// B layout (v[k] = elem t*16+k): element bits 0-3 (strides 1,2,4,8).
// A layout (v[k] = elem k*64+t): element bits 6-9 (strides 64..512).
__device__ __forceinline__ void fwht_reg16(float v[KK]) {
#pragma unroll
    for (int b = 1; b < KK; b <<= 1) {
#pragma unroll
        for (int k = 0; k < KK; k++) {
            if ((k & b) == 0) {
                float a0 = v[k], a1 = v[k | b];
                v[k]     = a0 + a1;
                v[k | b] = a0 - a1;
            }
        }
    }
}

// Cross-lane butterfly for element bits 4,5 (= lane bits 0,1) in B layout.
__device__ __forceinline__ void fwht_shfl(float v[KK], int lane, int m) {
#pragma unroll
    for (int k = 0; k < KK; k++) {
        float w = __shfl_xor_sync(0xffffffffu, v[k], m);
        v[k] = (lane & m) ? (w - v[k]) : (v[k] + w);
    }
}

__global__ __launch_bounds__(THREADS, 4)   // <=128 regs; v[4][16] resident
void FastFoodLayerDense_kernel(const float* __restrict__ x,
                               const float* __restrict__ Bm,
                               const float* __restrict__ G,
                               const float* __restrict__ S,
                               const float* __restrict__ bias,
                               const int*   __restrict__ P,
                               float*       __restrict__ out,
                               int nrows)
{
    // one buffer per (unit, row) — R8 addressing, scalar shared ops
    __shared__ float sh[UNITS][RR][SHSZ];   // 33.8 KB

    const int tid  = threadIdx.x;
    const int u    = tid >> 6;                       // unit within block
    const int t    = tid & 63;                       // thread within unit
    const int lane = tid & 31;
    const int s    = ((blockIdx.x & 1) << 1) | u;    // stack index
    const int r0   = (blockIdx.x >> 1) * RR;         // first row of quad

    // addr(e) = e + (e>>5)  (R6/R8-proven):
    //  B layout e = t*16+k -> 16t + (t>>1) + k
    //  A layout e = k*64+t -> 66k + t + (t>>5)
    const int bBase = 16 * t + (t >> 1);
    const int aOff  = t + (t >> 5);

    int rows[RR];
    bool wr[RR];
#pragma unroll
    for (int r = 0; r < RR; r++) {
        int rr = r0 + r;
        wr[r]   = rr < nrows;
        rows[r] = wr[r] ? rr : (nrows - 1);   // clamp loads, guard stores
    }

    float v[RR][KK];

    // ===== load x*B (B layout, vectorized; B loaded once per quad) =====
    const float4* Bv = (const float4*)(Bm + s * DD);
#pragma unroll
    for (int j = 0; j < 4; j++) {
        float4 bv = Bv[t * 4 + j];
#pragma unroll
        for (int r = 0; r < RR; r++) {
            const float4* xv = (const float4*)(x + (size_t)rows[r] * DD);
            float4 a = xv[t * 4 + j];
            v[r][4*j+0] = a.x * bv.x;  v[r][4*j+1] = a.y * bv.y;
            v[r][4*j+2] = a.z * bv.z;  v[r][4*j+3] = a.w * bv.w;
        }
    }

    // ===== WHT #1 low: bits 0-3 (reg) + 4,5 (shfl) =====
#pragma unroll
    for (int r = 0; r < RR; r++) {
        fwht_reg16(v[r]);
        fwht_shfl(v[r], lane, 1);
        fwht_shfl(v[r], lane, 2);
    }

    // ===== RT1: B -> A =====
#pragma unroll
    for (int r = 0; r < RR; r++)
#pragma unroll
        for (int k = 0; k < KK; k++)
            sh[u][r][bBase + k] = v[r][k];
    __syncthreads();
#pragma unroll
    for (int r = 0; r < RR; r++)
#pragma unroll
        for (int k = 0; k < KK; k++)
            v[r][k] = sh[u][r][66 * k + aOff];

    // ===== WHT #1 high: bits 6-9 =====
#pragma unroll
    for (int r = 0; r < RR; r++) fwht_reg16(v[r]);

    // ===== RT2: stage element-ordered, then permute-gather * G =====
    __syncthreads();                       // WAR on buffers
#pragma unroll
    for (int r = 0; r < RR; r++)
#pragma unroll
        for (int k = 0; k < KK; k++)
            sh[u][r][66 * k + aOff] = v[r][k];
    __syncthreads();

    const int*   Ps = P + s * DD;
    const float* Gs = G + s * DD;
#pragma unroll
    for (int k = 0; k < KK; k++) {
        int e = k * 64 + t;
        int p = Ps[e] - s * DD;            // segment s maps within stack s
        int pp = p + (p >> 5);
        float g = Gs[e];                   // P,G loaded once per quad
#pragma unroll
        for (int r = 0; r < RR; r++)
            v[r][k] = sh[u][r][pp] * g;
    }

    // ===== WHT #2 high: bits 6-9 (A layout) =====
#pragma unroll
    for (int r = 0; r < RR; r++) fwht_reg16(v[r]);

    // ===== RT3: A -> B =====
    __syncthreads();                       // WAR on buffers
#pragma unroll
    for (int r = 0; r < RR; r++)
#pragma unroll
        for (int k = 0; k < KK; k++)
            sh[u][r][66 * k + aOff] = v[r][k];
    __syncthreads();
#pragma unroll
    for (int r = 0; r < RR; r++)
#pragma unroll
        for (int k = 0; k < KK; k++)
            v[r][k] = sh[u][r][bBase + k];

    // ===== WHT #2 low: bits 0-3 (reg) + 4,5 (shfl) =====
#pragma unroll
    for (int r = 0; r < RR; r++) {
        fwht_reg16(v[r]);
        fwht_shfl(v[r], lane, 1);
        fwht_shfl(v[r], lane, 2);
    }

    // ===== scale, cos/sin, vectorized stores (S/bias loaded once per quad) =====
    const float4* S4  = (const float4*)(S + s * DD);
    const float4* bc4 = (const float4*)(bias + s * DD);
    const float4* bs4 = (const float4*)(bias + STACK * DD + s * DD);
    const float scale = 0.03125f;   // 1/(sigma*sqrt(D))
    const float amp   = 0.03125f;   // sqrt(1/D)
#pragma unroll
    for (int j = 0; j < 4; j++) {
        float4 sv = S4[t * 4 + j];
        float4 bc = bc4[t * 4 + j];
        float4 bs = bs4[t * 4 + j];
#pragma unroll
        for (int r = 0; r < RR; r++) {
            if (!wr[r]) continue;
            float sn, cs;
            float4 co, si;
            __sincosf(v[r][4*j+0] * (scale * sv.x), &sn, &cs);
            co.x = fmaf(amp, cs, bc.x);  si.x = fmaf(amp, sn, bs.x);
            __sincosf(v[r][4*j+1] * (scale * sv.y), &sn, &cs);
            co.y = fmaf(amp, cs, bc.y);  si.y = fmaf(amp, sn, bs.y);
            __sincosf(v[r][4*j+2] * (scale * sv.z), &sn, &cs);
            co.z = fmaf(amp, cs, bc.z);  si.z = fmaf(amp, sn, bs.z);
            __sincosf(v[r][4*j+3] * (scale * sv.w), &sn, &cs);
            co.w = fmaf(amp, cs, bc.w);  si.w = fmaf(amp, sn, bs.w);
            float* orow = out + (size_t)rows[r] * (2 * STACK * DD);
            ((float4*)(orow + s * DD))[t * 4 + j]              = co;
            ((float4*)(orow + STACK * DD + s * DD))[t * 4 + j] = si;
        }
    }
}

extern "C" void kernel_launch(void* const* d_in, const int* in_sizes, int n_in,
                              void* d_out, int out_size)
{
    // metadata order: x, B, G, S, bias, H (unused), P
    const float* x    = (const float*)d_in[0];
    const float* Bm   = (const float*)d_in[1];
    const float* G    = (const float*)d_in[2];
    const float* S    = (const float*)d_in[3];
    const float* bias = (const float*)d_in[4];
    const int*   P    = (const int*)  d_in[6];

    int nrows  = in_sizes[0] / DD;                 // 8192
    int quads  = (nrows + RR - 1) / RR;            // 2048
    int blocks = quads * (STACK / UNITS);          // 4096 (2 stack-units/block)

    FastFoodLayerDense_kernel<<<blocks, THREADS>>>(
        x, Bm, G, S, bias, P, (float*)d_out, nrows);
}

// round 12
// speedup vs baseline: 2.7971x; 1.0291x over previous
#include <cuda_runtime.h>
#include <math.h>

#define DD      1024
#define KK      16      // elements per thread per row
#define RR      4       // rows per unit (quad batching, float4-interleaved)
#define UNITS   2       // stack-units per block
#define THREADS 128
#define STACK   4
#define SH4     1088    // float4 slots per unit buffer: max addr4(1023)=1086

// In-register FWHT over the 4 bits of k.
// B layout (v[k] = elem t*16+k): element bits 0-3 (strides 1,2,4,8).
// A layout (v[k] = elem k*64+t): element bits 6-9 (strides 64..512).
__device__ __forceinline__ void fwht_reg16(float v[KK]) {
#pragma unroll
    for (int b = 1; b < KK; b <<= 1) {
#pragma unroll
        for (int k = 0; k < KK; k++) {
            if ((k & b) == 0) {
                float a0 = v[k], a1 = v[k | b];
                v[k]     = a0 + a1;
                v[k | b] = a0 - a1;
            }
        }
    }
}

// Cross-lane butterfly for element bits 4,5 (= lane bits 0,1) in B layout.
__device__ __forceinline__ void fwht_shfl(float v[KK], int lane, int m) {
#pragma unroll
    for (int k = 0; k < KK; k++) {
        float w = __shfl_xor_sync(0xffffffffu, v[k], m);
        v[k] = (lane & m) ? (w - v[k]) : (v[k] + w);
    }
}

// Padded float4 addressing: addr4(e) = e + (e>>4)
//  B sweep e = 16t+k (k<16): addr4 = 17t + k            (17t mod 8 distinct/phase)
//  A sweep e = 64k+t:        addr4 = 68k + t + (t>>4)   (lane-consecutive)
//  gather  e = p:            addr4 = p + (p>>4)

__global__ __launch_bounds__(THREADS, 4)   // <=128 regs; v[4][16] resident
void FastFoodLayerDense_kernel(const float* __restrict__ x,
                               const float* __restrict__ Bm,
                               const float* __restrict__ G,
                               const float* __restrict__ S,
                               const float* __restrict__ bias,
                               const int*   __restrict__ P,
                               float*       __restrict__ out,
                               int nrows)
{
    // native float4 buffer: rows interleaved per element, no type punning
    __shared__ float4 sh[UNITS][SH4];   // 34.8 KB

    const int tid  = threadIdx.x;
    const int u    = tid >> 6;                       // unit within block
    const int t    = tid & 63;                       // thread within unit
    const int lane = tid & 31;
    const int s    = ((blockIdx.x & 1) << 1) | u;    // stack index
    const int r0   = (blockIdx.x >> 1) * RR;         // first row of quad

    const int bBase = 17 * t;              // B-sweep float4 base
    const int aOff  = t + (t >> 4);        // A-sweep float4 offset

    float4* shu = sh[u];

    int rows[RR];
    bool wr[RR];
#pragma unroll
    for (int r = 0; r < RR; r++) {
        int rr = r0 + r;
        wr[r]   = rr < nrows;
        rows[r] = wr[r] ? rr : (nrows - 1);   // clamp loads, guard stores
    }

    float v[RR][KK];

    // ===== load x*B (B layout, vectorized; B loaded once per quad) =====
    const float4* Bv = (const float4*)(Bm + s * DD);
#pragma unroll
    for (int j = 0; j < 4; j++) {
        float4 bv = Bv[t * 4 + j];
#pragma unroll
        for (int r = 0; r < RR; r++) {
            const float4* xv = (const float4*)(x + (size_t)rows[r] * DD);
            float4 a = xv[t * 4 + j];
            v[r][4*j+0] = a.x * bv.x;  v[r][4*j+1] = a.y * bv.y;
            v[r][4*j+2] = a.z * bv.z;  v[r][4*j+3] = a.w * bv.w;
        }
    }

    // ===== WHT #1 low: bits 0-3 (reg) + 4,5 (shfl) =====
#pragma unroll
    for (int r = 0; r < RR; r++) {
        fwht_reg16(v[r]);
        fwht_shfl(v[r], lane, 1);
        fwht_shfl(v[r], lane, 2);
    }

    // ===== RT1: B -> A (row-interleaved STS.128/LDS.128) =====
#pragma unroll
    for (int k = 0; k < KK; k++)
        shu[bBase + k] = make_float4(v[0][k], v[1][k], v[2][k], v[3][k]);
    __syncthreads();
#pragma unroll
    for (int k = 0; k < KK; k++) {
        float4 a = shu[68 * k + aOff];
        v[0][k] = a.x;  v[1][k] = a.y;  v[2][k] = a.z;  v[3][k] = a.w;
    }

    // ===== WHT #1 high: bits 6-9 =====
#pragma unroll
    for (int r = 0; r < RR; r++) fwht_reg16(v[r]);

    // ===== RT2: stage element-ordered (A layout), then permute-gather * G =====
    __syncthreads();                       // WAR on buffer
#pragma unroll
    for (int k = 0; k < KK; k++)
        shu[68 * k + aOff] = make_float4(v[0][k], v[1][k], v[2][k], v[3][k]);
    __syncthreads();

    const int*   Ps = P + s * DD;
    const float* Gs = G + s * DD;
#pragma unroll
    for (int k = 0; k < KK; k++) {
        int e = k * 64 + t;
        int p = Ps[e] - s * DD;            // segment s maps within stack s
        float4 a = shu[p + (p >> 4)];      // one LDS.128 serves all 4 rows
        float g  = Gs[e];
        v[0][k] = a.x * g;  v[1][k] = a.y * g;
        v[2][k] = a.z * g;  v[3][k] = a.w * g;
    }

    // ===== WHT #2 high: bits 6-9 (A layout) =====
#pragma unroll
    for (int r = 0; r < RR; r++) fwht_reg16(v[r]);

    // ===== RT3: A -> B =====
    __syncthreads();                       // WAR on buffer
#pragma unroll
    for (int k = 0; k < KK; k++)
        shu[68 * k + aOff] = make_float4(v[0][k], v[1][k], v[2][k], v[3][k]);
    __syncthreads();
#pragma unroll
    for (int k = 0; k < KK; k++) {
        float4 a = shu[bBase + k];
        v[0][k] = a.x;  v[1][k] = a.y;  v[2][k] = a.z;  v[3][k] = a.w;
    }

    // ===== WHT #2 low: bits 0-3 (reg) + 4,5 (shfl) =====
#pragma unroll
    for (int r = 0; r < RR; r++) {
        fwht_reg16(v[r]);
        fwht_shfl(v[r], lane, 1);
        fwht_shfl(v[r], lane, 2);
    }

    // ===== scale, cos/sin, vectorized stores (S/bias loaded once per quad) =====
    const float4* S4  = (const float4*)(S + s * DD);
    const float4* bc4 = (const float4*)(bias + s * DD);
    const float4* bs4 = (const float4*)(bias + STACK * DD + s * DD);
    const float scale = 0.03125f;   // 1/(sigma*sqrt(D))
    const float amp   = 0.03125f;   // sqrt(1/D)
#pragma unroll
    for (int j = 0; j < 4; j++) {
        float4 sv = S4[t * 4 + j];
        float4 bc = bc4[t * 4 + j];
        float4 bs = bs4[t * 4 + j];
#pragma unroll
        for (int r = 0; r < RR; r++) {
            if (!wr[r]) continue;
            float sn, cs;
            float4 co, si;
            __sincosf(v[r][4*j+0] * (scale * sv.x), &sn, &cs);
            co.x = fmaf(amp, cs, bc.x);  si.x = fmaf(amp, sn, bs.x);
            __sincosf(v[r][4*j+1] * (scale * sv.y), &sn, &cs);
            co.y = fmaf(amp, cs, bc.y);  si.y = fmaf(amp, sn, bs.y);
            __sincosf(v[r][4*j+2] * (scale * sv.z), &sn, &cs);
            co.z = fmaf(amp, cs, bc.z);  si.z = fmaf(amp, sn, bs.z);
            __sincosf(v[r][4*j+3] * (scale * sv.w), &sn, &cs);
            co.w = fmaf(amp, cs, bc.w);  si.w = fmaf(amp, sn, bs.w);
            float* orow = out + (size_t)rows[r] * (2 * STACK * DD);
            ((float4*)(orow + s * DD))[t * 4 + j]              = co;
            ((float4*)(orow + STACK * DD + s * DD))[t * 4 + j] = si;
        }
    }
}

extern "C" void kernel_launch(void* const* d_in, const int* in_sizes, int n_in,
                              void* d_out, int out_size)
{
    // metadata order: x, B, G, S, bias, H (unused), P
    const float* x    = (const float*)d_in[0];
    const float* Bm   = (const float*)d_in[1];
    const float* G    = (const float*)d_in[2];
    const float* S    = (const float*)d_in[3];
    const float* bias = (const float*)d_in[4];
    const int*   P    = (const int*)  d_in[6];

    int nrows  = in_sizes[0] / DD;                 // 8192
    int quads  = (nrows + RR - 1) / RR;            // 2048
    int blocks = quads * (STACK / UNITS);          // 4096 (2 stack-units/block)

    FastFoodLayerDense_kernel<<<blocks, THREADS>>>(
        x, Bm, G, S, bias, P, (float*)d_out, nrows);
}

// round 14
// speedup vs baseline: 3.0442x; 1.0883x over previous
#include <cuda_runtime.h>
#include <math.h>

#define DD      1024
#define KK      8       // elements per thread per row
#define RR      4       // rows per unit (quad batching, float4-interleaved)
#define UNITS   2       // stack-units per block
#define UT      128     // threads per unit (4 warps)
#define THREADS (UNITS * UT)
#define STACK   4
#define SH4     1160    // float4 slots per unit: max addr4(1023)=1150

// In-register FWHT over the 3 bits of k (8 values).
__device__ __forceinline__ void fwht_reg8(float v[KK]) {
#pragma unroll
    for (int b = 1; b < KK; b <<= 1) {
#pragma unroll
        for (int k = 0; k < KK; k++) {
            if ((k & b) == 0) {
                float a0 = v[k], a1 = v[k | b];
                v[k]     = a0 + a1;
                v[k | b] = a0 - a1;
            }
        }
    }
}

// Cross-lane butterfly: element bit (3+log2 m) == lane bit log2 m in B layout.
__device__ __forceinline__ void fwht_shfl(float v[KK], int lane, int m) {
#pragma unroll
    for (int k = 0; k < KK; k++) {
        float w = __shfl_xor_sync(0xffffffffu, v[k], m);
        v[k] = (lane & m) ? (w - v[k]) : (v[k] + w);
    }
}

// Padded float4 addressing: addr4(e) = e + (e>>3)
//  B sweep e = 8t+k (k<8): addr4 = 9t + k              ((t+k) mod 8 distinct per phase)
//  A sweep e = 128k+t:     addr4 = 144k + t + (t>>3)   (lane-consecutive)
//  gather  e = p:          addr4 = p + (p>>3)

__global__ __launch_bounds__(THREADS, 3)   // <=85 regs; v[4][8] resident
void FastFoodLayerDense_kernel(const float* __restrict__ x,
                               const float* __restrict__ Bm,
                               const float* __restrict__ G,
                               const float* __restrict__ S,
                               const float* __restrict__ bias,
                               const int*   __restrict__ P,
                               float*       __restrict__ out,
                               int nrows)
{
    __shared__ float4 sh[UNITS][SH4];   // 37.1 KB

    const int tid  = threadIdx.x;
    const int u    = tid >> 7;                       // unit within block
    const int t    = tid & 127;                      // thread within unit
    const int lane = tid & 31;
    const int s    = ((blockIdx.x & 1) << 1) | u;    // stack index
    const int r0   = (blockIdx.x >> 1) * RR;         // first row of quad

    const int bBase = 9 * t;               // B-sweep float4 base
    const int aOff  = t + (t >> 3);        // A-sweep float4 offset

    float4* shu = sh[u];

    int rows[RR];
    bool wr[RR];
#pragma unroll
    for (int r = 0; r < RR; r++) {
        int rr = r0 + r;
        wr[r]   = rr < nrows;
        rows[r] = wr[r] ? rr : (nrows - 1);   // clamp loads, guard stores
    }

    float v[RR][KK];

    // ===== load x*B (B layout e = 8t+k, vectorized; B loaded once per quad) =====
    const float4* Bv = (const float4*)(Bm + s * DD);
#pragma unroll
    for (int j = 0; j < 2; j++) {
        float4 bv = Bv[t * 2 + j];
#pragma unroll
        for (int r = 0; r < RR; r++) {
            const float4* xv = (const float4*)(x + (size_t)rows[r] * DD);
            float4 a = xv[t * 2 + j];
            v[r][4*j+0] = a.x * bv.x;  v[r][4*j+1] = a.y * bv.y;
            v[r][4*j+2] = a.z * bv.z;  v[r][4*j+3] = a.w * bv.w;
        }
    }

    // ===== WHT #1 low: bits 0-2 (reg) + 3-6 (shfl) =====
#pragma unroll
    for (int r = 0; r < RR; r++) {
        fwht_reg8(v[r]);
        fwht_shfl(v[r], lane, 1);
        fwht_shfl(v[r], lane, 2);
        fwht_shfl(v[r], lane, 4);
        fwht_shfl(v[r], lane, 8);
    }

    // ===== RT1: B -> A (row-interleaved STS.128/LDS.128) =====
#pragma unroll
    for (int k = 0; k < KK; k++)
        shu[bBase + k] = make_float4(v[0][k], v[1][k], v[2][k], v[3][k]);
    __syncthreads();
#pragma unroll
    for (int k = 0; k < KK; k++) {
        float4 a = shu[144 * k + aOff];
        v[0][k] = a.x;  v[1][k] = a.y;  v[2][k] = a.z;  v[3][k] = a.w;
    }

    // ===== WHT #1 high: bits 7-9 (A layout, regs) =====
#pragma unroll
    for (int r = 0; r < RR; r++) fwht_reg8(v[r]);

    // ===== RT2: stage element-ordered (A layout), then permute-gather * G =====
    __syncthreads();                       // WAR on buffer
#pragma unroll
    for (int k = 0; k < KK; k++)
        shu[144 * k + aOff] = make_float4(v[0][k], v[1][k], v[2][k], v[3][k]);
    __syncthreads();

    const int*   Ps = P + s * DD;
    const float* Gs = G + s * DD;
#pragma unroll
    for (int k = 0; k < KK; k++) {
        int e = k * 128 + t;
        int p = Ps[e] - s * DD;            // segment s maps within stack s
        float4 a = shu[p + (p >> 3)];      // one LDS.128 serves all 4 rows
        float g  = Gs[e];
        v[0][k] = a.x * g;  v[1][k] = a.y * g;
        v[2][k] = a.z * g;  v[3][k] = a.w * g;
    }

    // ===== WHT #2 high: bits 7-9 (A layout) =====
#pragma unroll
    for (int r = 0; r < RR; r++) fwht_reg8(v[r]);

    // ===== RT3: A -> B =====
    __syncthreads();                       // WAR on buffer
#pragma unroll
    for (int k = 0; k < KK; k++)
        shu[144 * k + aOff] = make_float4(v[0][k], v[1][k], v[2][k], v[3][k]);
    __syncthreads();
#pragma unroll
    for (int k = 0; k < KK; k++) {
        float4 a = shu[bBase + k];
        v[0][k] = a.x;  v[1][k] = a.y;  v[2][k] = a.z;  v[3][k] = a.w;
    }

    // ===== WHT #2 low: bits 0-2 (reg) + 3-6 (shfl) =====
#pragma unroll
    for (int r = 0; r < RR; r++) {
        fwht_reg8(v[r]);
        fwht_shfl(v[r], lane, 1);
        fwht_shfl(v[r], lane, 2);
        fwht_shfl(v[r], lane, 4);
        fwht_shfl(v[r], lane, 8);
    }

    // ===== scale, cos/sin, vectorized stores (S/bias loaded once per quad) =====
    const float4* S4  = (const float4*)(S + s * DD);
    const float4* bc4 = (const float4*)(bias + s * DD);
    const float4* bs4 = (const float4*)(bias + STACK * DD + s * DD);
    const float scale = 0.03125f;   // 1/(sigma*sqrt(D))
    const float amp   = 0.03125f;   // sqrt(1/D)
#pragma unroll
    for (int j = 0; j < 2; j++) {
        float4 sv = S4[t * 2 + j];
        float4 bc = bc4[t * 2 + j];
        float4 bs = bs4[t * 2 + j];
#pragma unroll
        for (int r = 0; r < RR; r++) {
            if (!wr[r]) continue;
            float sn, cs;
            float4 co, si;
            __sincosf(v[r][4*j+0] * (scale * sv.x), &sn, &cs);
            co.x = fmaf(amp, cs, bc.x);  si.x = fmaf(amp, sn, bs.x);
            __sincosf(v[r][4*j+1] * (scale * sv.y), &sn, &cs);
            co.y = fmaf(amp, cs, bc.y);  si.y = fmaf(amp, sn, bs.y);
            __sincosf(v[r][4*j+2] * (scale * sv.z), &sn, &cs);
            co.z = fmaf(amp, cs, bc.z);  si.z = fmaf(amp, sn, bs.z);
            __sincosf(v[r][4*j+3] * (scale * sv.w), &sn, &cs);
            co.w = fmaf(amp, cs, bc.w);  si.w = fmaf(amp, sn, bs.w);
            float* orow = out + (size_t)rows[r] * (2 * STACK * DD);
            ((float4*)(orow + s * DD))[t * 2 + j]              = co;
            ((float4*)(orow + STACK * DD + s * DD))[t * 2 + j] = si;
        }
    }
}

extern "C" void kernel_launch(void* const* d_in, const int* in_sizes, int n_in,
                              void* d_out, int out_size)
{
    // metadata order: x, B, G, S, bias, H (unused), P
    const float* x    = (const float*)d_in[0];
    const float* Bm   = (const float*)d_in[1];
    const float* G    = (const float*)d_in[2];
    const float* S    = (const float*)d_in[3];
    const float* bias = (const float*)d_in[4];
    const int*   P    = (const int*)  d_in[6];

    int nrows  = in_sizes[0] / DD;                 // 8192
    int quads  = (nrows + RR - 1) / RR;            // 2048
    int blocks = quads * (STACK / UNITS);          // 4096 (2 stack-units/block)

    FastFoodLayerDense_kernel<<<blocks, THREADS>>>(
        x, Bm, G, S, bias, P, (float*)d_out, nrows);
}